// round 15
// baseline (speedup 1.0000x reference)
#include <cuda_runtime.h>
#include <cuda_fp16.h>
#include <cstdint>

#define IN_CH   256
#define OUT_CH  256
#define HID     128
#define S_MAX   16384
#define N_MAX   1100000

// ---- gate kernel smem geometry (fp16 elems), BK=64 ----
#define TSA     72            // A tile stride (64 k + 8 pad)
#define SB      136           // B tile stride (128 n + 8 pad)
#define TA_OFF  0
#define TB_OFF  9216          // 128*72
#define TBUF    17920         // 9216 + 64*136
#define G_SMEM  71680         // 2 buffers * 17920 * 2B
#define TSST    133           // fp32 staging stride (gate epilogue unused)

// ---- transform kernel smem geometry (fp16 elems) ----
#define RSA     264           // resident A stride (256 k + 8 pad)
#define RA_ELEMS 33792        // 128*264
#define BB_OFF  33792         // B stream area starts after resident A
#define BBUF2   8704          // 64*136 per buffer
#define TR_SMEM 102400        // (33792 + 2*8704) * 2B
#define STST    136           // fp16 staging stride (overlays B area)

// ---------------- scratch (device globals: no allocation allowed) ----------
__device__ float g_e[N_MAX];
__device__ float g_segsum[S_MAX];
__device__ int   g_idx64;
// X converted to fp16 by the gate kernel; consumed by the transform kernel.
// Rows >= n are never written and stay zero-initialized (safe to MMA).
__device__ __align__(16) __half g_Xh[(size_t)N_MAX * IN_CH];
// weights [k][n] row-major, single fp16 copy
__device__ __align__(16) __half g_W1h[IN_CH * HID];
__device__ __align__(16) __half g_Wth[IN_CH * OUT_CH];

// ---------------- helpers ---------------------------------------------------
__device__ __forceinline__ int load_idx(const void* idx, int i) {
    if (g_idx64) return (int)((const long long*)idx)[i];
    return ((const int*)idx)[i];
}

#define LDSM4(R, ADDR)                                                        \
    asm volatile("ldmatrix.sync.aligned.m8n8.x4.shared.b16 {%0,%1,%2,%3},[%4];" \
                 : "=r"(R[0]), "=r"(R[1]), "=r"(R[2]), "=r"(R[3]) : "r"(ADDR))
#define LDSM4T(R, ADDR)                                                       \
    asm volatile("ldmatrix.sync.aligned.m8n8.x4.trans.shared.b16 {%0,%1,%2,%3},[%4];" \
                 : "=r"(R[0]), "=r"(R[1]), "=r"(R[2]), "=r"(R[3]) : "r"(ADDR))
#define MMA_F16(C, A, B0, B1)                                                 \
    asm volatile("mma.sync.aligned.m16n8k16.row.col.f32.f16.f16.f32 "         \
                 "{%0,%1,%2,%3},{%4,%5,%6,%7},{%8,%9},{%0,%1,%2,%3};"         \
                 : "+f"(C[0]), "+f"(C[1]), "+f"(C[2]), "+f"(C[3])             \
                 : "r"(A[0]), "r"(A[1]), "r"(A[2]), "r"(A[3]),                \
                   "r"(B0), "r"(B1))
#define CP16(DST, SRC)                                                        \
    asm volatile("cp.async.ca.shared.global [%0],[%1],16;\n"                  \
                 :: "r"(DST), "l"(__cvta_generic_to_global(SRC)))
#define CP_COMMIT() asm volatile("cp.async.commit_group;")
#define CP_WAIT0()  asm volatile("cp.async.wait_group 0;")

// ---------------- setup kernel (detect + init + convert fused) --------------
__global__ void setup_kernel(const void* __restrict__ idx, int n,
                             const float* __restrict__ W1,
                             const float* __restrict__ Wt) {
    int i = blockIdx.x * blockDim.x + threadIdx.x;
    if (i == 0) {
        const long long* p = (const long long*)idx;
        int base = n / 4;
        int ok64 = 1;
        for (int j = 0; j < 8; j++) {
            long long v = p[base + j];
            if (v < 0 || v >= (1LL << 31)) ok64 = 0;
        }
        g_idx64 = ok64;
    }
    if (i < S_MAX) g_segsum[i] = 0.f;
    if (i < IN_CH * OUT_CH) g_Wth[i] = __float2half_rn(Wt[i]);
    if (i < IN_CH * HID)    g_W1h[i] = __float2half_rn(W1[i]);
}

// ---------------- gate kernel (BK=64; shuffle-reduce epilogue) ---------------
// Unchanged from round 12 (proven: ~330 us).
__global__ __launch_bounds__(256, 2) void gate_kernel(
    const float* __restrict__ X, const void* __restrict__ idx,
    const float* __restrict__ b1,
    const float* __restrict__ W2, const float* __restrict__ b2, int n)
{
    extern __shared__ __half sm[];
    __shared__ float red[256];
    __shared__ float sb1[128];
    __shared__ float sw2[128];

    const int tid  = threadIdx.x;
    const int lane = tid & 31;
    const int warp = tid >> 5;
    const int warpRow = (warp & 3) * 32;
    const int warpCol = (warp >> 2) * 64;
    const int rowBase = blockIdx.x * 128;

    const uint32_t smemBase = (uint32_t)__cvta_generic_to_shared(sm);

    if (tid < 128) { sb1[tid] = b1[tid]; sw2[tid] = W2[tid]; }

    float acc[2][8][4];
#pragma unroll
    for (int mt = 0; mt < 2; mt++)
#pragma unroll
        for (int nt = 0; nt < 8; nt++)
#pragma unroll
            for (int q = 0; q < 4; q++) acc[mt][nt][q] = 0.f;

    float4 aPref[8];

    auto loadA = [&](int kt) {
#pragma unroll
        for (int u = 0; u < 8; u++) {
            int f = tid + 256 * u;
            int row = f >> 4, kq = f & 15;
            int gr = rowBase + row;
            aPref[u] = (gr < n)
                ? *(const float4*)(X + (size_t)gr * IN_CH + kt * 64 + kq * 4)
                : make_float4(0.f, 0.f, 0.f, 0.f);
        }
    };
    auto stsA = [&](int b, int kt) {
#pragma unroll
        for (int u = 0; u < 8; u++) {
            int f = tid + 256 * u;
            int row = f >> 4, kq = f & 15;
            float4 v = aPref[u];
            __half2 h0 = __floats2half2_rn(v.x, v.y);
            __half2 h1 = __floats2half2_rn(v.z, v.w);
            uint2 hp = make_uint2(*(uint32_t*)&h0, *(uint32_t*)&h1);
            int off = b * TBUF + TA_OFF + row * TSA + kq * 4;
            *(uint2*)&sm[off] = hp;
            int gr = rowBase + row;
            if (gr < n)
                *(uint2*)&g_Xh[(size_t)gr * IN_CH + kt * 64 + kq * 4] = hp;
        }
    };
    auto cpB = [&](int b, int kt) {
#pragma unroll
        for (int u = 0; u < 4; u++) {
            int e = tid + 256 * u;
            int krow = e >> 4, c16 = e & 15;
            const __half* src = g_W1h + (size_t)(kt * 64 + krow) * HID + c16 * 8;
            uint32_t dst = smemBase +
                (uint32_t)(b * TBUF + TB_OFF + krow * SB + c16 * 8) * 2u;
            CP16(dst, src);
        }
    };
    auto compute = [&](int b) {
#pragma unroll
        for (int kk = 0; kk < 64; kk += 16) {
            uint32_t ah[2][4];
#pragma unroll
            for (int mt = 0; mt < 2; mt++) {
                int row = warpRow + mt * 16 + (lane & 15);
                int kof = kk + ((lane >> 4) << 3);
                LDSM4(ah[mt], smemBase +
                    (uint32_t)(b * TBUF + TA_OFF + row * TSA + kof) * 2u);
            }
#pragma unroll
            for (int p = 0; p < 4; p++) {
                int krow = kk + (lane & 7) + (((lane >> 3) & 1) << 3);
                int ncol = warpCol + p * 16 + ((lane >> 4) << 3);
                uint32_t bh[4];
                LDSM4T(bh, smemBase +
                    (uint32_t)(b * TBUF + TB_OFF + krow * SB + ncol) * 2u);
                MMA_F16(acc[0][2 * p],     ah[0], bh[0], bh[1]);
                MMA_F16(acc[1][2 * p],     ah[1], bh[0], bh[1]);
                MMA_F16(acc[0][2 * p + 1], ah[0], bh[2], bh[3]);
                MMA_F16(acc[1][2 * p + 1], ah[1], bh[2], bh[3]);
            }
        }
    };

    loadA(0);
    cpB(0, 0);
    CP_COMMIT();
    stsA(0, 0);
    CP_WAIT0();
    __syncthreads();

#pragma unroll 1
    for (int kt = 0; kt < 4; kt++) {
        int cur = kt & 1;
        bool more = (kt < 3);
        if (more) {
            loadA(kt + 1);
            cpB(1 - cur, kt + 1);
            CP_COMMIT();
        }
        compute(cur);
        if (more) {
            stsA(1 - cur, kt + 1);
            CP_WAIT0();
        }
        __syncthreads();
    }

#pragma unroll
    for (int mt = 0; mt < 2; mt++) {
        float p0 = 0.f, p1 = 0.f;
#pragma unroll
        for (int nt = 0; nt < 8; nt++) {
            int c0 = warpCol + nt * 8 + ((lane & 3) << 1);
            p0 += fmaxf(acc[mt][nt][0] + sb1[c0],     0.f) * sw2[c0];
            p0 += fmaxf(acc[mt][nt][1] + sb1[c0 + 1], 0.f) * sw2[c0 + 1];
            p1 += fmaxf(acc[mt][nt][2] + sb1[c0],     0.f) * sw2[c0];
            p1 += fmaxf(acc[mt][nt][3] + sb1[c0 + 1], 0.f) * sw2[c0 + 1];
        }
        p0 += __shfl_xor_sync(0xffffffffu, p0, 1);
        p0 += __shfl_xor_sync(0xffffffffu, p0, 2);
        p1 += __shfl_xor_sync(0xffffffffu, p1, 1);
        p1 += __shfl_xor_sync(0xffffffffu, p1, 2);
        if ((lane & 3) == 0) {
            int r = warpRow + mt * 16 + (lane >> 2);
            red[r * 2 + (warp >> 2)]       = p0;
            red[(r + 8) * 2 + (warp >> 2)] = p1;
        }
    }
    __syncthreads();

    if (tid < 128) {
        int gr = rowBase + tid;
        if (gr < n) {
            float g = b2[0] + red[tid * 2] + red[tid * 2 + 1];
            float e = expf(g);           // gate is O(1): no max-shift needed
            g_e[gr] = e;
            int s = load_idx(idx, gr);
            atomicAdd(&g_segsum[s], e);
        }
    }
}

// ---------------- transform kernel: resident A, two N-half phases -----------
// A (128x256 fp16) loaded ONCE into smem; B streamed per half (4 chunks of
// BK=64, double buffered -> 16KB fills). Epilogue stages t in fp16 overlaid
// on the dead B buffers, then sorted segmented scan with fp32 alpha.
__global__ __launch_bounds__(256, 2) void transform_kernel(
    const void* __restrict__ idx, const float* __restrict__ bt,
    float* __restrict__ out, int n)
{
    extern __shared__ __half sm[];
    __shared__ int   sidx[128];
    __shared__ float srow[128];

    const int tid  = threadIdx.x;
    const int lane = tid & 31;
    const int warp = tid >> 5;
    const int warpRow = (warp & 3) * 32;
    const int warpCol = (warp >> 2) * 64;
    const int rowBase = blockIdx.x * 128;

    const uint32_t smemBase = (uint32_t)__cvta_generic_to_shared(sm);

    // ---- prologue: resident A fill (cp.async), alpha/idx load ----
    {
        // 128 rows x 32 granules (16B = 8 halves) = 4096; 16 per thread
#pragma unroll
        for (int u = 0; u < 16; u++) {
            int g = tid + 256 * u;
            int row = g >> 5, kq = g & 31;
            const __half* s = g_Xh + (size_t)(rowBase + row) * IN_CH + kq * 8;
            uint32_t dst = smemBase + (uint32_t)(row * RSA + kq * 8) * 2u;
            CP16(dst, s);
        }
        CP_COMMIT();
    }
    if (tid < 128) {
        int gr = rowBase + tid;
        if (gr < n) {
            int s = load_idx(idx, gr);
            sidx[tid] = s;
            srow[tid] = g_e[gr] / fmaxf(g_segsum[s], 1e-16f);
        } else { sidx[tid] = -1; srow[tid] = 0.f; }
    }

    auto fillB = [&](int b, int kt, int nBase) {
        // 64 krows x 16 granules = 1024; 4 per thread
#pragma unroll
        for (int u = 0; u < 4; u++) {
            int e = tid + 256 * u;
            int krow = e >> 4, c16 = e & 15;
            const __half* s =
                g_Wth + (size_t)(kt * 64 + krow) * OUT_CH + nBase + c16 * 8;
            uint32_t dst = smemBase +
                (uint32_t)(BB_OFF + b * BBUF2 + krow * SB + c16 * 8) * 2u;
            CP16(dst, s);
        }
    };
    auto compute = [&](int b, int kt, float (&acc)[2][8][4]) {
#pragma unroll
        for (int kk = 0; kk < 64; kk += 16) {
            uint32_t ah[2][4];
#pragma unroll
            for (int mt = 0; mt < 2; mt++) {
                int row = warpRow + mt * 16 + (lane & 15);
                int k   = kt * 64 + kk + ((lane >> 4) << 3);
                LDSM4(ah[mt], smemBase + (uint32_t)(row * RSA + k) * 2u);
            }
#pragma unroll
            for (int p = 0; p < 4; p++) {
                int krow = kk + (lane & 7) + (((lane >> 3) & 1) << 3);
                int ncol = warpCol + p * 16 + ((lane >> 4) << 3);
                uint32_t bh[4];
                LDSM4T(bh, smemBase +
                    (uint32_t)(BB_OFF + b * BBUF2 + krow * SB + ncol) * 2u);
                MMA_F16(acc[0][2 * p],     ah[0], bh[0], bh[1]);
                MMA_F16(acc[1][2 * p],     ah[1], bh[0], bh[1]);
                MMA_F16(acc[0][2 * p + 1], ah[0], bh[2], bh[3]);
                MMA_F16(acc[1][2 * p + 1], ah[1], bh[2], bh[3]);
            }
        }
    };

    __half* Ts = sm + BB_OFF;   // fp16 staging overlays the B stream buffers

#pragma unroll 1
    for (int h = 0; h < 2; h++) {
        const int nBase = h * 128;
        float acc[2][8][4];
#pragma unroll
        for (int mt = 0; mt < 2; mt++)
#pragma unroll
            for (int nt = 0; nt < 8; nt++)
#pragma unroll
                for (int q = 0; q < 4; q++) acc[mt][nt][q] = 0.f;

        fillB(0, 0, nBase);
        CP_COMMIT();
        CP_WAIT0();             // A (h=0) + B chunk 0 landed
        __syncthreads();

#pragma unroll 1
        for (int kt = 0; kt < 4; kt++) {
            int cur = kt & 1;
            bool more = (kt < 3);
            if (more) {
                fillB(1 - cur, kt + 1, nBase);
                CP_COMMIT();
            }
            compute(cur, kt, acc);
            if (more) CP_WAIT0();
            __syncthreads();
        }

        // ---- epilogue: stage t = relu(acc + bt) as fp16 in dead B area ----
#pragma unroll
        for (int mt = 0; mt < 2; mt++)
#pragma unroll
            for (int nt = 0; nt < 8; nt++) {
                int r0 = warpRow + mt * 16 + (lane >> 2);
                int c0 = warpCol + nt * 8 + ((lane & 3) << 1);
                float b0 = bt[nBase + c0], b1v = bt[nBase + c0 + 1];
                __half2 t0 = __floats2half2_rn(
                    fmaxf(acc[mt][nt][0] + b0,  0.f),
                    fmaxf(acc[mt][nt][1] + b1v, 0.f));
                __half2 t1 = __floats2half2_rn(
                    fmaxf(acc[mt][nt][2] + b0,  0.f),
                    fmaxf(acc[mt][nt][3] + b1v, 0.f));
                *(__half2*)&Ts[r0 * STST + c0]       = t0;
                *(__half2*)&Ts[(r0 + 8) * STST + c0] = t1;
            }
        __syncthreads();

        // ---- sorted segmented column scan (weight = fp32 alpha) ----
        {
            int c = tid & 127;
            int rStart = (tid >> 7) * 64;
            float a = 0.f;
            int prev = -1;
            for (int r = rStart; r < rStart + 64; r++) {
                int s = sidx[r];
                if (s < 0) break;
                if (s != prev) {
                    if (prev >= 0)
                        atomicAdd(&out[(size_t)prev * OUT_CH + nBase + c], a);
                    a = 0.f;
                    prev = s;
                }
                a = fmaf(__half2float(Ts[r * STST + c]), srow[r], a);
            }
            if (prev >= 0)
                atomicAdd(&out[(size_t)prev * OUT_CH + nBase + c], a);
        }
        __syncthreads();        // staging area reused by next half's B fill
    }
}

// ---------------- launch -----------------------------------------------------
extern "C" void kernel_launch(void* const* d_in, const int* in_sizes, int n_in,
                              void* d_out, int out_size)
{
    const float* X   = (const float*)d_in[0];
    const void*  idx = d_in[1];
    int base = (n_in >= 9 && in_sizes[2] <= 16) ? 3 : 2;
    const float* W1 = (const float*)d_in[base + 0];
    const float* b1 = (const float*)d_in[base + 1];
    const float* W2 = (const float*)d_in[base + 2];
    const float* b2 = (const float*)d_in[base + 3];
    const float* Wt = (const float*)d_in[base + 4];
    const float* bt = (const float*)d_in[base + 5];

    const int n = in_sizes[0] / IN_CH;
    float* out = (float*)d_out;

    cudaFuncSetAttribute(gate_kernel,
                         cudaFuncAttributeMaxDynamicSharedMemorySize, G_SMEM);
    cudaFuncSetAttribute(transform_kernel,
                         cudaFuncAttributeMaxDynamicSharedMemorySize, TR_SMEM);

    cudaMemsetAsync(d_out, 0, (size_t)out_size * sizeof(float), 0);
    setup_kernel<<<(IN_CH * OUT_CH + 255) / 256, 256>>>(idx, n, W1, Wt);

    const int nTiles = (n + 127) / 128;
    gate_kernel<<<dim3(nTiles, 1), 256, G_SMEM>>>(X, idx, b1, W2, b2, n);
    transform_kernel<<<dim3(nTiles, 1), 256, TR_SMEM>>>(idx, bt, out, n);
}